// round 12
// baseline (speedup 1.0000x reference)
#include <cuda_runtime.h>
#include <cuda_fp16.h>
#include <cstdint>

#define N_NODES 100000
#define N_EDGES 1600000
#define HID 64

#define SCAN_BLK 1024
#define N_SCAN_BLOCKS ((N_NODES + SCAN_BLK - 1) / SCAN_BLK)   // 98

// ---- device-global scratch (no allocations allowed) ----
__device__ __half g_xwh[(size_t)N_NODES * HID];
__device__ int    g_deg[N_NODES];
__device__ int    g_off[N_NODES + 1];
__device__ int    g_col[N_EDGES];
__device__ int    g_agg[N_SCAN_BLOCKS];    // decoupled-lookback state
__device__ int    g_pref[N_SCAN_BLOCKS];
__device__ int    g_flag[N_SCAN_BLOCKS];   // 0=empty 1=agg 2=prefix
__device__ int    g_idx_is64;

// ---------------------------------------------------------------------------
// One kernel: zero g_deg, zero lookback flags, detect index dtype (warp ballot).
// ---------------------------------------------------------------------------
__global__ __launch_bounds__(256) void csr_init(const int* __restrict__ ei_raw) {
    int i = blockIdx.x * 256 + threadIdx.x;
    if (i < N_NODES) g_deg[i] = 0;
    if (i < N_SCAN_BLOCKS) g_flag[i] = 0;
    if (blockIdx.x == 0 && threadIdx.x < 32) {
        // each lane checks 8 consecutive int64 candidates
        int bad = 0;
        #pragma unroll
        for (int j = 0; j < 8; j++) {
            int idx = threadIdx.x * 8 + j;
            int lo = ei_raw[2 * idx];
            int hi = ei_raw[2 * idx + 1];
            if (hi != 0 || (unsigned)lo >= (unsigned)N_NODES) bad = 1;
        }
        unsigned m = __ballot_sync(0xffffffffu, bad);
        if (threadIdx.x == 0) g_idx_is64 = (m == 0) ? 1 : 0;
    }
}

// ---------------------------------------------------------------------------
// CSR build: 4 edges per thread, vectorized index loads.
// ---------------------------------------------------------------------------
__global__ __launch_bounds__(256) void count_deg(const int* __restrict__ ei) {
    int e = (blockIdx.x * 256 + threadIdx.x) * 4;
    if (e >= N_EDGES) return;
    int d[4];
    if (g_idx_is64) {
        int4 v0 = *(const int4*)&ei[2 * ((size_t)N_EDGES + e)];
        int4 v1 = *(const int4*)&ei[2 * ((size_t)N_EDGES + e) + 4];
        d[0] = v0.x; d[1] = v0.z; d[2] = v1.x; d[3] = v1.z;
    } else {
        int4 v = *(const int4*)&ei[(size_t)N_EDGES + e];
        d[0] = v.x; d[1] = v.y; d[2] = v.z; d[3] = v.w;
    }
    #pragma unroll
    for (int k = 0; k < 4; k++) atomicAdd(&g_deg[d[k]], 1);
}

// ---------------------------------------------------------------------------
// Single-pass exclusive scan with decoupled lookback.
// Writes g_off, resets g_deg to 0 (fill cursors), sets g_off[N_NODES].
// ---------------------------------------------------------------------------
__global__ __launch_bounds__(SCAN_BLK) void scan_lookback() {
    __shared__ int warpsums[32];
    __shared__ int s_run;
    const int tid = threadIdx.x, lane = tid & 31, wid = tid >> 5;
    const int bid = blockIdx.x;
    const int i = bid * SCAN_BLK + tid;

    int v = (i < N_NODES) ? g_deg[i] : 0;
    int s = v;
    #pragma unroll
    for (int d = 1; d < 32; d <<= 1) {
        int t = __shfl_up_sync(0xffffffffu, s, d);
        if (lane >= d) s += t;
    }
    if (lane == 31) warpsums[wid] = s;
    __syncthreads();
    if (wid == 0) {
        int ws = warpsums[lane];
        #pragma unroll
        for (int d = 1; d < 32; d <<= 1) {
            int t = __shfl_up_sync(0xffffffffu, ws, d);
            if (lane >= d) ws += t;
        }
        warpsums[lane] = ws;
    }
    __syncthreads();
    int warpoff = (wid == 0) ? 0 : warpsums[wid - 1];
    int exc = warpoff + s - v;             // block-local exclusive prefix
    int tot = warpsums[31];                // block total

    // publish aggregate / run lookback (thread 0)
    if (tid == 0) {
        volatile int* vflag = g_flag;
        if (bid == 0) {
            g_pref[0] = tot;
            __threadfence();
            vflag[0] = 2;
            s_run = 0;
        } else {
            g_agg[bid] = tot;
            __threadfence();
            vflag[bid] = 1;
            int run = 0;
            for (int j = bid - 1; j >= 0; j--) {
                int f;
                do { f = vflag[j]; } while (f == 0);
                __threadfence();            // order payload read after flag
                if (f == 2) { run += g_pref[j]; break; }
                run += g_agg[j];
            }
            g_pref[bid] = run + tot;
            __threadfence();
            vflag[bid] = 2;
            s_run = run;
        }
    }
    __syncthreads();
    int run = s_run;

    if (i < N_NODES) {
        g_off[i] = run + exc;
        g_deg[i] = 0;
    }
    if (bid == N_SCAN_BLOCKS - 1 && tid == 0)
        g_off[N_NODES] = run + tot;
}

__global__ __launch_bounds__(256) void fill_csr(const int* __restrict__ ei) {
    int e = (blockIdx.x * 256 + threadIdx.x) * 4;
    if (e >= N_EDGES) return;
    int s[4], d[4];
    if (g_idx_is64) {
        int4 sv0 = *(const int4*)&ei[2 * (size_t)e];
        int4 sv1 = *(const int4*)&ei[2 * (size_t)e + 4];
        int4 dv0 = *(const int4*)&ei[2 * ((size_t)N_EDGES + e)];
        int4 dv1 = *(const int4*)&ei[2 * ((size_t)N_EDGES + e) + 4];
        s[0] = sv0.x; s[1] = sv0.z; s[2] = sv1.x; s[3] = sv1.z;
        d[0] = dv0.x; d[1] = dv0.z; d[2] = dv1.x; d[3] = dv1.z;
    } else {
        int4 sv = *(const int4*)&ei[(size_t)e];
        int4 dv = *(const int4*)&ei[(size_t)N_EDGES + e];
        s[0] = sv.x; s[1] = sv.y; s[2] = sv.z; s[3] = sv.w;
        d[0] = dv.x; d[1] = dv.y; d[2] = dv.z; d[3] = dv.w;
    }
    #pragma unroll
    for (int k = 0; k < 4; k++)
        g_col[g_off[d[k]] + atomicAdd(&g_deg[d[k]], 1)] = s[k];
}

// ---------------------------------------------------------------------------
// Tensor-core GEMM: Y[n,0..63] = X[n,0..K-1] @ W[K,64], Y stored fp16.
// mma.sync.m16n8k16, fp32 accumulate. W split hi/lo (error cancels to ~fp32).
// ---------------------------------------------------------------------------
template <int K>
__global__ __launch_bounds__(256) void gemm_mma(const float* __restrict__ X,
                                                const float* __restrict__ W,
                                                __half* __restrict__ Y,
                                                int nrows) {
    __shared__ __half sA [128][72];
    __shared__ __half sBh[64][72];
    __shared__ __half sBl[64][72];

    const int tid  = threadIdx.x;
    const int w    = tid >> 5;
    const int lane = tid & 31;
    const int row0 = blockIdx.x * 128;

    float d[8][4];
    #pragma unroll
    for (int nb = 0; nb < 8; nb++)
        #pragma unroll
        for (int r = 0; r < 4; r++) d[nb][r] = 0.f;

    for (int kc = 0; kc < K; kc += 64) {
        __syncthreads();
        #pragma unroll
        for (int j = 0; j < 8; j++) {
            int idx = j * 256 + tid;
            int r = idx >> 4, c4 = idx & 15;
            int grow = row0 + r;
            float4 v = (grow < nrows)
                     ? *(const float4*)&X[(size_t)grow * K + kc + c4 * 4]
                     : make_float4(0.f, 0.f, 0.f, 0.f);
            *(__half2*)&sA[r][c4 * 4]     = __floats2half2_rn(v.x, v.y);
            *(__half2*)&sA[r][c4 * 4 + 2] = __floats2half2_rn(v.z, v.w);
        }
        #pragma unroll
        for (int j = 0; j < 4; j++) {
            int idx = j * 256 + tid;
            int k = idx >> 4, c4 = idx & 15;
            float4 v = *(const float4*)&W[(size_t)(kc + k) * 64 + c4 * 4];
            __half hx = __float2half_rn(v.x), hy = __float2half_rn(v.y);
            __half hz = __float2half_rn(v.z), hw = __float2half_rn(v.w);
            *(__half2*)&sBh[k][c4 * 4]     = __halves2half2(hx, hy);
            *(__half2*)&sBh[k][c4 * 4 + 2] = __halves2half2(hz, hw);
            __half lx = __float2half_rn(v.x - __half2float(hx));
            __half ly = __float2half_rn(v.y - __half2float(hy));
            __half lz = __float2half_rn(v.z - __half2float(hz));
            __half lw = __float2half_rn(v.w - __half2float(hw));
            *(__half2*)&sBl[k][c4 * 4]     = __halves2half2(lx, ly);
            *(__half2*)&sBl[k][c4 * 4 + 2] = __halves2half2(lz, lw);
        }
        __syncthreads();

        #pragma unroll
        for (int ks = 0; ks < 64; ks += 16) {
            uint32_t a0, a1, a2, a3;
            {
                int m = lane >> 3;
                int arow = w * 16 + (m & 1) * 8 + (lane & 7);
                int acol = ks + (m >> 1) * 8;
                uint32_t sa = (uint32_t)__cvta_generic_to_shared(&sA[arow][acol]);
                asm volatile("ldmatrix.sync.aligned.m8n8.x4.shared.b16 "
                             "{%0,%1,%2,%3}, [%4];"
                             : "=r"(a0), "=r"(a1), "=r"(a2), "=r"(a3) : "r"(sa));
            }
            #pragma unroll
            for (int nb2 = 0; nb2 < 4; nb2++) {
                int n0 = nb2 * 16;
                int m = lane >> 3;
                int brow = ks + (m & 1) * 8 + (lane & 7);
                int bcol = n0 + (m >> 1) * 8;
                uint32_t bh0, bh1, bh2, bh3, bl0, bl1, bl2, bl3;
                uint32_t sbh = (uint32_t)__cvta_generic_to_shared(&sBh[brow][bcol]);
                uint32_t sbl = (uint32_t)__cvta_generic_to_shared(&sBl[brow][bcol]);
                asm volatile("ldmatrix.sync.aligned.m8n8.x4.trans.shared.b16 "
                             "{%0,%1,%2,%3}, [%4];"
                             : "=r"(bh0), "=r"(bh1), "=r"(bh2), "=r"(bh3) : "r"(sbh));
                asm volatile("ldmatrix.sync.aligned.m8n8.x4.trans.shared.b16 "
                             "{%0,%1,%2,%3}, [%4];"
                             : "=r"(bl0), "=r"(bl1), "=r"(bl2), "=r"(bl3) : "r"(sbl));
                float* dA = d[nb2 * 2];
                float* dB = d[nb2 * 2 + 1];
                asm volatile("mma.sync.aligned.m16n8k16.row.col.f32.f16.f16.f32 "
                             "{%0,%1,%2,%3}, {%4,%5,%6,%7}, {%8,%9}, {%0,%1,%2,%3};"
                             : "+f"(dA[0]), "+f"(dA[1]), "+f"(dA[2]), "+f"(dA[3])
                             : "r"(a0), "r"(a1), "r"(a2), "r"(a3), "r"(bh0), "r"(bh1));
                asm volatile("mma.sync.aligned.m16n8k16.row.col.f32.f16.f16.f32 "
                             "{%0,%1,%2,%3}, {%4,%5,%6,%7}, {%8,%9}, {%0,%1,%2,%3};"
                             : "+f"(dA[0]), "+f"(dA[1]), "+f"(dA[2]), "+f"(dA[3])
                             : "r"(a0), "r"(a1), "r"(a2), "r"(a3), "r"(bl0), "r"(bl1));
                asm volatile("mma.sync.aligned.m16n8k16.row.col.f32.f16.f16.f32 "
                             "{%0,%1,%2,%3}, {%4,%5,%6,%7}, {%8,%9}, {%0,%1,%2,%3};"
                             : "+f"(dB[0]), "+f"(dB[1]), "+f"(dB[2]), "+f"(dB[3])
                             : "r"(a0), "r"(a1), "r"(a2), "r"(a3), "r"(bh2), "r"(bh3));
                asm volatile("mma.sync.aligned.m16n8k16.row.col.f32.f16.f16.f32 "
                             "{%0,%1,%2,%3}, {%4,%5,%6,%7}, {%8,%9}, {%0,%1,%2,%3};"
                             : "+f"(dB[0]), "+f"(dB[1]), "+f"(dB[2]), "+f"(dB[3])
                             : "r"(a0), "r"(a1), "r"(a2), "r"(a3), "r"(bl2), "r"(bl3));
            }
        }
    }

    int g = lane >> 2;
    int r0 = row0 + w * 16 + g;
    int r1 = r0 + 8;
    int cb = (lane & 3) * 2;
    #pragma unroll
    for (int nb = 0; nb < 8; nb++) {
        int c = nb * 8 + cb;
        if (r0 < nrows) {
            __half2 h = __floats2half2_rn(d[nb][0], d[nb][1]);
            *(uint32_t*)&Y[(size_t)r0 * 64 + c] = *(uint32_t*)&h;
        }
        if (r1 < nrows) {
            __half2 h = __floats2half2_rn(d[nb][2], d[nb][3]);
            *(uint32_t*)&Y[(size_t)r1 * 64 + c] = *(uint32_t*)&h;
        }
    }
}

// ---------------------------------------------------------------------------
// CSR gather-aggregate (R9 form): fp16 rows, fp32 accumulate.
// ---------------------------------------------------------------------------
__global__ __launch_bounds__(256) void gather64(const __half* __restrict__ xw,
                                                float* __restrict__ out,
                                                const float* __restrict__ b) {
    int node = (blockIdx.x * 256 + threadIdx.x) >> 5;
    if (node >= N_NODES) return;
    const int lane = threadIdx.x & 31;
    const int half = lane >> 4;
    const int q    = lane & 15;

    const int beg = __ldg(&g_off[node]);
    const int end = __ldg(&g_off[node + 1]);

    float4 acc = make_float4(0.f, 0.f, 0.f, 0.f);
    int i = beg + half;
    int nxt = (i < end) ? __ldg(&g_col[i]) : 0;
    while (i < end) {
        int src = nxt;
        int j = i + 2;
        if (j < end) nxt = __ldg(&g_col[j]);
        uint2 raw = *reinterpret_cast<const uint2*>(xw + (size_t)src * 64 + q * 4);
        float2 f0 = __half22float2(*reinterpret_cast<__half2*>(&raw.x));
        float2 f1 = __half22float2(*reinterpret_cast<__half2*>(&raw.y));
        acc.x += f0.x; acc.y += f0.y; acc.z += f1.x; acc.w += f1.y;
        i = j;
    }
    acc.x += __shfl_xor_sync(0xffffffffu, acc.x, 16);
    acc.y += __shfl_xor_sync(0xffffffffu, acc.y, 16);
    acc.z += __shfl_xor_sync(0xffffffffu, acc.z, 16);
    acc.w += __shfl_xor_sync(0xffffffffu, acc.w, 16);

    if (half == 0) {
        float4 bv = reinterpret_cast<const float4*>(b)[q];
        acc.x += bv.x; acc.y += bv.y; acc.z += bv.z; acc.w += bv.w;
        *reinterpret_cast<float4*>(out + (size_t)node * 64 + q * 4) = acc;
    }
}

// ---------------------------------------------------------------------------
extern "C" void kernel_launch(void* const* d_in, const int* in_sizes, int n_in,
                              void* d_out, int out_size) {
    const float* x  = (const float*)d_in[0];
    const int*   ei = (const int*)d_in[1];
    const float* W1 = (const float*)d_in[2];
    const float* b1 = (const float*)d_in[3];
    const float* W2 = (const float*)d_in[4];
    const float* b2 = (const float*)d_in[5];
    const float* W3 = (const float*)d_in[6];
    const float* b3 = (const float*)d_in[7];

    float* h1 = (float*)d_out;
    float* h2 = h1 + (size_t)N_NODES * HID;
    float* h3 = h2 + (size_t)N_NODES * HID;

    __half* xw;
    cudaGetSymbolAddress((void**)&xw, g_xwh);

    const int ggrid  = (N_NODES + 127) / 128;
    const int e4grid = (N_EDGES / 4 + 255) / 256;
    const int ngrid  = (N_NODES + 255) / 256;
    const int agrid  = (N_NODES * 32 + 255) / 256;

    static cudaStream_t sB = nullptr;
    static cudaEvent_t  ev_fork = nullptr, ev_csr = nullptr;
    if (sB == nullptr) {
        cudaStreamCreateWithFlags(&sB, cudaStreamNonBlocking);
        cudaEventCreateWithFlags(&ev_fork, cudaEventDisableTiming);
        cudaEventCreateWithFlags(&ev_csr,  cudaEventDisableTiming);
    }

    // --- Fork: CSR build (4 kernels) on stream B, GEMM1 on main stream ---
    cudaEventRecord(ev_fork, 0);
    cudaStreamWaitEvent(sB, ev_fork, 0);

    csr_init<<<ngrid, 256, 0, sB>>>(ei);
    count_deg<<<e4grid, 256, 0, sB>>>(ei);
    scan_lookback<<<N_SCAN_BLOCKS, SCAN_BLK, 0, sB>>>();
    fill_csr<<<e4grid, 256, 0, sB>>>(ei);
    cudaEventRecord(ev_csr, sB);

    gemm_mma<128><<<ggrid, 256>>>(x, W1, xw, N_NODES);   // main stream

    cudaStreamWaitEvent(0, ev_csr, 0);     // gather1 needs CSR + xw

    // --- serial layers ---
    gather64<<<agrid, 256>>>(xw, h1, b1);
    gemm_mma<64><<<ggrid, 256>>>(h1, W2, xw, N_NODES);
    gather64<<<agrid, 256>>>(xw, h2, b2);
    gemm_mma<64><<<ggrid, 256>>>(h2, W3, xw, N_NODES);
    gather64<<<agrid, 256>>>(xw, h3, b3);
}

// round 13
// speedup vs baseline: 1.0931x; 1.0931x over previous
#include <cuda_runtime.h>
#include <cuda_fp16.h>
#include <cstdint>

#define N_NODES 100000
#define N_EDGES 1600000
#define HID 64

#define SCAN_BLK 1024
#define N_SCAN_BLOCKS ((N_NODES + SCAN_BLK - 1) / SCAN_BLK)   // 98

// ---- device-global scratch (no allocations allowed) ----
__device__ __half g_xwh[(size_t)N_NODES * HID];
__device__ int    g_deg[N_NODES];          // counts -> fill cursors (= offsets)
__device__ int    g_off[N_NODES + 1];      // CSR row offsets (by dst)
__device__ int    g_col[N_EDGES];
__device__ int    g_part[N_SCAN_BLOCKS];
__device__ int    g_idx_is64;

// ---------------------------------------------------------------------------
// Zero g_deg + detect edge-index dtype (warp ballot) in one launch.
// ---------------------------------------------------------------------------
__global__ __launch_bounds__(256) void csr_init(const int* __restrict__ ei_raw) {
    int i = blockIdx.x * 256 + threadIdx.x;
    if (i < N_NODES) g_deg[i] = 0;
    if (blockIdx.x == 0 && threadIdx.x < 32) {
        int bad = 0;
        #pragma unroll
        for (int j = 0; j < 8; j++) {
            int idx = threadIdx.x * 8 + j;
            int lo = ei_raw[2 * idx];
            int hi = ei_raw[2 * idx + 1];
            if (hi != 0 || (unsigned)lo >= (unsigned)N_NODES) bad = 1;
        }
        unsigned m = __ballot_sync(0xffffffffu, bad);
        if (threadIdx.x == 0) g_idx_is64 = (m == 0) ? 1 : 0;
    }
}

// ---------------------------------------------------------------------------
// CSR build: 2 edges per thread (R11 config — more warps hide atomic latency).
// ---------------------------------------------------------------------------
__global__ __launch_bounds__(256) void count_deg(const int* __restrict__ ei) {
    int e = (blockIdx.x * 256 + threadIdx.x) * 2;
    if (e >= N_EDGES) return;
    int d0, d1;
    if (g_idx_is64) {
        int4 v = *(const int4*)&ei[2 * ((size_t)N_EDGES + e)];
        d0 = v.x; d1 = v.z;
    } else {
        int2 v = *(const int2*)&ei[(size_t)N_EDGES + e];
        d0 = v.x; d1 = v.y;
    }
    atomicAdd(&g_deg[d0], 1);
    atomicAdd(&g_deg[d1], 1);
}

// A) per-block exclusive scan; block total -> g_part[b]   (R11 proven)
__global__ __launch_bounds__(SCAN_BLK) void scan_blocks() {
    __shared__ int warpsums[32];
    const int tid = threadIdx.x, lane = tid & 31, wid = tid >> 5;
    const int i = blockIdx.x * SCAN_BLK + tid;

    int v = (i < N_NODES) ? g_deg[i] : 0;
    int s = v;
    #pragma unroll
    for (int d = 1; d < 32; d <<= 1) {
        int t = __shfl_up_sync(0xffffffffu, s, d);
        if (lane >= d) s += t;
    }
    if (lane == 31) warpsums[wid] = s;
    __syncthreads();
    if (wid == 0) {
        int ws = warpsums[lane];
        #pragma unroll
        for (int d = 1; d < 32; d <<= 1) {
            int t = __shfl_up_sync(0xffffffffu, ws, d);
            if (lane >= d) ws += t;
        }
        warpsums[lane] = ws;
    }
    __syncthreads();
    int warpoff = (wid == 0) ? 0 : warpsums[wid - 1];
    if (i < N_NODES) g_off[i] = warpoff + s - v;
    if (tid == SCAN_BLK - 1) g_part[blockIdx.x] = warpsums[31];
}

// B+C) add block offsets; set g_deg = offset (CURSOR TRICK: fill_csr then
// needs no g_off read — atomicAdd on the cursor directly yields the slot).
__global__ __launch_bounds__(SCAN_BLK) void scan_finish() {
    __shared__ int soff;
    const int tid = threadIdx.x;
    if (tid < 32) {
        int sum = 0;
        for (int j = tid; j < blockIdx.x; j += 32) sum += g_part[j];
        #pragma unroll
        for (int d = 16; d > 0; d >>= 1)
            sum += __shfl_xor_sync(0xffffffffu, sum, d);
        if (tid == 0) soff = sum;
    }
    __syncthreads();
    int off = soff;
    int i = blockIdx.x * SCAN_BLK + tid;
    if (i < N_NODES) {
        int o = g_off[i] + off;
        g_off[i] = o;
        g_deg[i] = o;              // cursor starts at the row offset
    }
    if (blockIdx.x == N_SCAN_BLOCKS - 1 && tid == 0)
        g_off[N_NODES] = off + g_part[N_SCAN_BLOCKS - 1];
}

__global__ __launch_bounds__(256) void fill_csr(const int* __restrict__ ei) {
    int e = (blockIdx.x * 256 + threadIdx.x) * 2;
    if (e >= N_EDGES) return;
    int s0, s1, d0, d1;
    if (g_idx_is64) {
        int4 sv = *(const int4*)&ei[2 * (size_t)e];
        int4 dv = *(const int4*)&ei[2 * ((size_t)N_EDGES + e)];
        s0 = sv.x; s1 = sv.z; d0 = dv.x; d1 = dv.z;
    } else {
        int2 sv = *(const int2*)&ei[(size_t)e];
        int2 dv = *(const int2*)&ei[(size_t)N_EDGES + e];
        s0 = sv.x; s1 = sv.y; d0 = dv.x; d1 = dv.y;
    }
    g_col[atomicAdd(&g_deg[d0], 1)] = s0;     // cursor == absolute slot
    g_col[atomicAdd(&g_deg[d1], 1)] = s1;
}

// ---------------------------------------------------------------------------
// Tensor-core GEMM: Y[n,0..63] = X[n,0..K-1] @ W[K,64], Y stored fp16.
// mma.sync.m16n8k16, fp32 accumulate. W split hi/lo (error cancels to ~fp32).
// ---------------------------------------------------------------------------
template <int K>
__global__ __launch_bounds__(256) void gemm_mma(const float* __restrict__ X,
                                                const float* __restrict__ W,
                                                __half* __restrict__ Y,
                                                int nrows) {
    __shared__ __half sA [128][72];
    __shared__ __half sBh[64][72];
    __shared__ __half sBl[64][72];

    const int tid  = threadIdx.x;
    const int w    = tid >> 5;
    const int lane = tid & 31;
    const int row0 = blockIdx.x * 128;

    float d[8][4];
    #pragma unroll
    for (int nb = 0; nb < 8; nb++)
        #pragma unroll
        for (int r = 0; r < 4; r++) d[nb][r] = 0.f;

    for (int kc = 0; kc < K; kc += 64) {
        __syncthreads();
        #pragma unroll
        for (int j = 0; j < 8; j++) {
            int idx = j * 256 + tid;
            int r = idx >> 4, c4 = idx & 15;
            int grow = row0 + r;
            float4 v = (grow < nrows)
                     ? *(const float4*)&X[(size_t)grow * K + kc + c4 * 4]
                     : make_float4(0.f, 0.f, 0.f, 0.f);
            *(__half2*)&sA[r][c4 * 4]     = __floats2half2_rn(v.x, v.y);
            *(__half2*)&sA[r][c4 * 4 + 2] = __floats2half2_rn(v.z, v.w);
        }
        #pragma unroll
        for (int j = 0; j < 4; j++) {
            int idx = j * 256 + tid;
            int k = idx >> 4, c4 = idx & 15;
            float4 v = *(const float4*)&W[(size_t)(kc + k) * 64 + c4 * 4];
            __half hx = __float2half_rn(v.x), hy = __float2half_rn(v.y);
            __half hz = __float2half_rn(v.z), hw = __float2half_rn(v.w);
            *(__half2*)&sBh[k][c4 * 4]     = __halves2half2(hx, hy);
            *(__half2*)&sBh[k][c4 * 4 + 2] = __halves2half2(hz, hw);
            __half lx = __float2half_rn(v.x - __half2float(hx));
            __half ly = __float2half_rn(v.y - __half2float(hy));
            __half lz = __float2half_rn(v.z - __half2float(hz));
            __half lw = __float2half_rn(v.w - __half2float(hw));
            *(__half2*)&sBl[k][c4 * 4]     = __halves2half2(lx, ly);
            *(__half2*)&sBl[k][c4 * 4 + 2] = __halves2half2(lz, lw);
        }
        __syncthreads();

        #pragma unroll
        for (int ks = 0; ks < 64; ks += 16) {
            uint32_t a0, a1, a2, a3;
            {
                int m = lane >> 3;
                int arow = w * 16 + (m & 1) * 8 + (lane & 7);
                int acol = ks + (m >> 1) * 8;
                uint32_t sa = (uint32_t)__cvta_generic_to_shared(&sA[arow][acol]);
                asm volatile("ldmatrix.sync.aligned.m8n8.x4.shared.b16 "
                             "{%0,%1,%2,%3}, [%4];"
                             : "=r"(a0), "=r"(a1), "=r"(a2), "=r"(a3) : "r"(sa));
            }
            #pragma unroll
            for (int nb2 = 0; nb2 < 4; nb2++) {
                int n0 = nb2 * 16;
                int m = lane >> 3;
                int brow = ks + (m & 1) * 8 + (lane & 7);
                int bcol = n0 + (m >> 1) * 8;
                uint32_t bh0, bh1, bh2, bh3, bl0, bl1, bl2, bl3;
                uint32_t sbh = (uint32_t)__cvta_generic_to_shared(&sBh[brow][bcol]);
                uint32_t sbl = (uint32_t)__cvta_generic_to_shared(&sBl[brow][bcol]);
                asm volatile("ldmatrix.sync.aligned.m8n8.x4.trans.shared.b16 "
                             "{%0,%1,%2,%3}, [%4];"
                             : "=r"(bh0), "=r"(bh1), "=r"(bh2), "=r"(bh3) : "r"(sbh));
                asm volatile("ldmatrix.sync.aligned.m8n8.x4.trans.shared.b16 "
                             "{%0,%1,%2,%3}, [%4];"
                             : "=r"(bl0), "=r"(bl1), "=r"(bl2), "=r"(bl3) : "r"(sbl));
                float* dA = d[nb2 * 2];
                float* dB = d[nb2 * 2 + 1];
                asm volatile("mma.sync.aligned.m16n8k16.row.col.f32.f16.f16.f32 "
                             "{%0,%1,%2,%3}, {%4,%5,%6,%7}, {%8,%9}, {%0,%1,%2,%3};"
                             : "+f"(dA[0]), "+f"(dA[1]), "+f"(dA[2]), "+f"(dA[3])
                             : "r"(a0), "r"(a1), "r"(a2), "r"(a3), "r"(bh0), "r"(bh1));
                asm volatile("mma.sync.aligned.m16n8k16.row.col.f32.f16.f16.f32 "
                             "{%0,%1,%2,%3}, {%4,%5,%6,%7}, {%8,%9}, {%0,%1,%2,%3};"
                             : "+f"(dA[0]), "+f"(dA[1]), "+f"(dA[2]), "+f"(dA[3])
                             : "r"(a0), "r"(a1), "r"(a2), "r"(a3), "r"(bl0), "r"(bl1));
                asm volatile("mma.sync.aligned.m16n8k16.row.col.f32.f16.f16.f32 "
                             "{%0,%1,%2,%3}, {%4,%5,%6,%7}, {%8,%9}, {%0,%1,%2,%3};"
                             : "+f"(dB[0]), "+f"(dB[1]), "+f"(dB[2]), "+f"(dB[3])
                             : "r"(a0), "r"(a1), "r"(a2), "r"(a3), "r"(bh2), "r"(bh3));
                asm volatile("mma.sync.aligned.m16n8k16.row.col.f32.f16.f16.f32 "
                             "{%0,%1,%2,%3}, {%4,%5,%6,%7}, {%8,%9}, {%0,%1,%2,%3};"
                             : "+f"(dB[0]), "+f"(dB[1]), "+f"(dB[2]), "+f"(dB[3])
                             : "r"(a0), "r"(a1), "r"(a2), "r"(a3), "r"(bl2), "r"(bl3));
            }
        }
    }

    int g = lane >> 2;
    int r0 = row0 + w * 16 + g;
    int r1 = r0 + 8;
    int cb = (lane & 3) * 2;
    #pragma unroll
    for (int nb = 0; nb < 8; nb++) {
        int c = nb * 8 + cb;
        if (r0 < nrows) {
            __half2 h = __floats2half2_rn(d[nb][0], d[nb][1]);
            *(uint32_t*)&Y[(size_t)r0 * 64 + c] = *(uint32_t*)&h;
        }
        if (r1 < nrows) {
            __half2 h = __floats2half2_rn(d[nb][2], d[nb][3]);
            *(uint32_t*)&Y[(size_t)r1 * 64 + c] = *(uint32_t*)&h;
        }
    }
}

// ---------------------------------------------------------------------------
// CSR gather-aggregate (R9 form): fp16 rows, fp32 accumulate.
// ---------------------------------------------------------------------------
__global__ __launch_bounds__(256) void gather64(const __half* __restrict__ xw,
                                                float* __restrict__ out,
                                                const float* __restrict__ b) {
    int node = (blockIdx.x * 256 + threadIdx.x) >> 5;
    if (node >= N_NODES) return;
    const int lane = threadIdx.x & 31;
    const int half = lane >> 4;
    const int q    = lane & 15;

    const int beg = __ldg(&g_off[node]);
    const int end = __ldg(&g_off[node + 1]);

    float4 acc = make_float4(0.f, 0.f, 0.f, 0.f);
    int i = beg + half;
    int nxt = (i < end) ? __ldg(&g_col[i]) : 0;
    while (i < end) {
        int src = nxt;
        int j = i + 2;
        if (j < end) nxt = __ldg(&g_col[j]);
        uint2 raw = *reinterpret_cast<const uint2*>(xw + (size_t)src * 64 + q * 4);
        float2 f0 = __half22float2(*reinterpret_cast<__half2*>(&raw.x));
        float2 f1 = __half22float2(*reinterpret_cast<__half2*>(&raw.y));
        acc.x += f0.x; acc.y += f0.y; acc.z += f1.x; acc.w += f1.y;
        i = j;
    }
    acc.x += __shfl_xor_sync(0xffffffffu, acc.x, 16);
    acc.y += __shfl_xor_sync(0xffffffffu, acc.y, 16);
    acc.z += __shfl_xor_sync(0xffffffffu, acc.z, 16);
    acc.w += __shfl_xor_sync(0xffffffffu, acc.w, 16);

    if (half == 0) {
        float4 bv = reinterpret_cast<const float4*>(b)[q];
        acc.x += bv.x; acc.y += bv.y; acc.z += bv.z; acc.w += bv.w;
        *reinterpret_cast<float4*>(out + (size_t)node * 64 + q * 4) = acc;
    }
}

// ---------------------------------------------------------------------------
extern "C" void kernel_launch(void* const* d_in, const int* in_sizes, int n_in,
                              void* d_out, int out_size) {
    const float* x  = (const float*)d_in[0];
    const int*   ei = (const int*)d_in[1];
    const float* W1 = (const float*)d_in[2];
    const float* b1 = (const float*)d_in[3];
    const float* W2 = (const float*)d_in[4];
    const float* b2 = (const float*)d_in[5];
    const float* W3 = (const float*)d_in[6];
    const float* b3 = (const float*)d_in[7];

    float* h1 = (float*)d_out;
    float* h2 = h1 + (size_t)N_NODES * HID;
    float* h3 = h2 + (size_t)N_NODES * HID;

    __half* xw;
    cudaGetSymbolAddress((void**)&xw, g_xwh);

    const int ggrid  = (N_NODES + 127) / 128;
    const int e2grid = (N_EDGES / 2 + 255) / 256;
    const int ngrid  = (N_NODES + 255) / 256;
    const int agrid  = (N_NODES * 32 + 255) / 256;

    static cudaStream_t sB = nullptr;
    static cudaEvent_t  ev_fork = nullptr, ev_csr = nullptr;
    if (sB == nullptr) {
        cudaStreamCreateWithFlags(&sB, cudaStreamNonBlocking);
        cudaEventCreateWithFlags(&ev_fork, cudaEventDisableTiming);
        cudaEventCreateWithFlags(&ev_csr,  cudaEventDisableTiming);
    }

    // --- Fork: CSR build on stream B, GEMM1 on main stream ---
    cudaEventRecord(ev_fork, 0);
    cudaStreamWaitEvent(sB, ev_fork, 0);

    csr_init<<<ngrid, 256, 0, sB>>>(ei);
    count_deg<<<e2grid, 256, 0, sB>>>(ei);
    scan_blocks<<<N_SCAN_BLOCKS, SCAN_BLK, 0, sB>>>();
    scan_finish<<<N_SCAN_BLOCKS, SCAN_BLK, 0, sB>>>();
    fill_csr<<<e2grid, 256, 0, sB>>>(ei);
    cudaEventRecord(ev_csr, sB);

    gemm_mma<128><<<ggrid, 256>>>(x, W1, xw, N_NODES);   // main stream

    cudaStreamWaitEvent(0, ev_csr, 0);     // gather1 needs CSR + xw

    // --- serial layers ---
    gather64<<<agrid, 256>>>(xw, h1, b1);
    gemm_mma<64><<<ggrid, 256>>>(h1, W2, xw, N_NODES);
    gather64<<<agrid, 256>>>(xw, h2, b2);
    gemm_mma<64><<<ggrid, 256>>>(h2, W3, xw, N_NODES);
    gather64<<<agrid, 256>>>(xw, h3, b3);
}